// round 13
// baseline (speedup 1.0000x reference)
#include <cuda_runtime.h>
#include <cstddef>

// Problem constants (fixed by the reference's module-level constants)
#define CN0   200000
#define CN1   100000
#define CN2   50000
#define CE0   1600000
#define CE1   800000
#define CIN_F 128
#define CH_F  256
#define CN_CLS 64

// ---------------------------------------------------------------------------
// Scratch (no allocation allowed -> __device__ globals)
// ---------------------------------------------------------------------------
__device__ float g_neigh1[(size_t)CN1 * CIN_F];   //  51.2 MB
__device__ float g_h1[(size_t)CN1 * CH_F];        // 102.4 MB
__device__ float g_neigh2[(size_t)CN2 * CH_F];    //  51.2 MB
__device__ int   g_idx64;                         // 1 if index arrays are int64

// ---------------------------------------------------------------------------
// Index-dtype probe. src0 is UNSORTED uniform in [0, 200000): if it were
// int64, every odd 32-bit word would be 0 (values < 2^31). Eight consecutive
// zero odd-words in an int32 array of uniform values has probability
// (1/200000)^8 ~ 4e-43. (Cannot probe the sorted dst arrays: their leading
// values are legitimately 0.) Deterministic: same input -> same flag.
// ---------------------------------------------------------------------------
__global__ void detect_idx_dtype(const int* __restrict__ src0_as_i32)
{
    bool i64 = true;
#pragma unroll
    for (int i = 0; i < 8; ++i)
        if (src0_as_i32[2 * i + 1] != 0) { i64 = false; break; }
    g_idx64 = i64 ? 1 : 0;
}

__device__ __forceinline__ int load_idx(const void* p, int i, bool i64)
{
    return i64 ? (int)__ldg(&((const long long*)p)[i])
               : __ldg(&((const int*)p)[i]);
}

// ---------------------------------------------------------------------------
// Segment-mean aggregation. dst[] is sorted ascending, so each destination's
// edges form a contiguous range found by binary search. One warp per dst row.
// FPL = float4's per lane (1 -> F=128 floats/row, 2 -> F=256 floats/row).
// UNROLL independent accumulator chains raise per-warp MLP (UNROLL rows of
// 512B/1KB in flight). UNROLL=4 for FPL=1 (16 f4 acc regs), 2 for FPL=2.
// Index dtype (int32/int64) resolved at runtime via g_idx64 (warp-uniform).
// ---------------------------------------------------------------------------
template <int FPL, int UNROLL>
__global__ void __launch_bounds__(256)
agg_mean_kernel(const float* __restrict__ h,
                const void* __restrict__ src,
                const void* __restrict__ dst,
                int num_edges, int num_dst,
                float* __restrict__ out)
{
    const int F = FPL * 128;
    int warp = (blockIdx.x * blockDim.x + threadIdx.x) >> 5;
    int lane = threadIdx.x & 31;
    if (warp >= num_dst) return;
    const int d = warp;
    const bool i64 = (g_idx64 != 0);

    // lower_bound(dst, d)
    int lo = 0, hi = num_edges;
    while (lo < hi) {
        int mid = (lo + hi) >> 1;
        if (load_idx(dst, mid, i64) < d) lo = mid + 1; else hi = mid;
    }
    const int start = lo;
    // upper_bound(dst, d)
    hi = num_edges;
    while (lo < hi) {
        int mid = (lo + hi) >> 1;
        if (load_idx(dst, mid, i64) <= d) lo = mid + 1; else hi = mid;
    }
    const int end = lo;

    float4 acc[UNROLL][FPL];
#pragma unroll
    for (int u = 0; u < UNROLL; ++u)
#pragma unroll
        for (int i = 0; i < FPL; ++i)
            acc[u][i] = make_float4(0.f, 0.f, 0.f, 0.f);

    int e = start;
    // Main loop: UNROLL edges per iteration, independent chains.
    for (; e + UNROLL - 1 < end; e += UNROLL) {
        const float4* rows[UNROLL];
#pragma unroll
        for (int u = 0; u < UNROLL; ++u) {
            int s = load_idx(src, e + u, i64);
            rows[u] = reinterpret_cast<const float4*>(h + (size_t)s * F);
        }
#pragma unroll
        for (int i = 0; i < FPL; ++i) {
#pragma unroll
            for (int u = 0; u < UNROLL; ++u) {
                float4 v = __ldg(&rows[u][lane + i * 32]);
                acc[u][i].x += v.x; acc[u][i].y += v.y;
                acc[u][i].z += v.z; acc[u][i].w += v.w;
            }
        }
    }
    // Remainder.
    for (; e < end; ++e) {
        int s = load_idx(src, e, i64);
        const float4* r = reinterpret_cast<const float4*>(h + (size_t)s * F);
#pragma unroll
        for (int i = 0; i < FPL; ++i) {
            float4 v = __ldg(&r[lane + i * 32]);
            acc[0][i].x += v.x; acc[0][i].y += v.y;
            acc[0][i].z += v.z; acc[0][i].w += v.w;
        }
    }

    int deg = end - start;
    float inv = 1.0f / (float)(deg > 1 ? deg : 1);
    float4* orow = reinterpret_cast<float4*>(out + (size_t)d * F);
#pragma unroll
    for (int i = 0; i < FPL; ++i) {
        float4 v = acc[0][i];
#pragma unroll
        for (int u = 1; u < UNROLL; ++u) {
            v.x += acc[u][i].x; v.y += acc[u][i].y;
            v.z += acc[u][i].z; v.w += acc[u][i].w;
        }
        v.x *= inv; v.y *= inv; v.z *= inv; v.w *= inv;
        orow[lane + i * 32] = v;
    }
}

// ---------------------------------------------------------------------------
// Dual-input GEMM, 128x128 tile, 8x8 per thread, split 4+4 fragments.
// Double-buffered smem (1 barrier per k-tile) + register prefetch of the
// next k-tile's global data.
//   C = A1 @ W1 + A2 @ W2 + bias  (+ReLU)
// A: [M,K] row-major, W: [K,N] row-major. Requires K%8==0, N%128==0.
// ---------------------------------------------------------------------------
template <bool RELU>
__global__ void __launch_bounds__(256, 2)
gemm_dual_128x128(const float* __restrict__ A1, const float* __restrict__ W1,
                  const float* __restrict__ A2, const float* __restrict__ W2,
                  const float* __restrict__ bias, float* __restrict__ C,
                  int M, int N, int K)
{
    constexpr int BM = 128, BN = 128, BK = 8;
    __shared__ float As[2][BK][BM + 4];
    __shared__ float Bs[2][BK][BN];

    const int tid = threadIdx.x;
    const int tx  = tid % 16;
    const int ty  = tid / 16;
    const int bm0 = blockIdx.x * BM;
    const int bn0 = blockIdx.y * BN;

    const int a_row = tid >> 1;        // 0..127
    const int a_f4  = tid & 1;         // which 16B of the 32B k-chunk
    const int b_row = tid >> 5;        // 0..7
    const int b_c4  = tid & 31;

    const bool a_in = (bm0 + a_row) < M;
    const size_t a_base = (size_t)(bm0 + a_row) * K + a_f4 * 4;
    const size_t b_base = (size_t)b_row * N + bn0 + b_c4 * 4;

    float acc[8][8];
#pragma unroll
    for (int i = 0; i < 8; ++i)
#pragma unroll
        for (int j = 0; j < 8; ++j) acc[i][j] = 0.f;

    const int NK = K / BK;             // k-tiles per phase
    const int total = 2 * NK;          // phases concatenated

    // Prologue: fetch tile 0 and commit to stage 0.
    {
        float4 pa = make_float4(0.f, 0.f, 0.f, 0.f);
        if (a_in) pa = *reinterpret_cast<const float4*>(A1 + a_base);
        float4 pb = *reinterpret_cast<const float4*>(W1 + b_base);
        As[0][a_f4 * 4 + 0][a_row] = pa.x;
        As[0][a_f4 * 4 + 1][a_row] = pa.y;
        As[0][a_f4 * 4 + 2][a_row] = pa.z;
        As[0][a_f4 * 4 + 3][a_row] = pa.w;
        *reinterpret_cast<float4*>(&Bs[0][b_row][b_c4 * 4]) = pb;
    }
    __syncthreads();

#pragma unroll 1
    for (int t = 0; t < total; ++t) {
        const int cur = t & 1;

        // Prefetch next tile (global -> registers) before compute.
        float4 pa, pb;
        const bool have_next = (t + 1 < total);
        if (have_next) {
            int nt = t + 1;
            const float* A = (nt < NK) ? A1 : A2;
            const float* W = (nt < NK) ? W1 : W2;
            int kt = (nt < NK ? nt : nt - NK) * BK;
            pa = make_float4(0.f, 0.f, 0.f, 0.f);
            if (a_in) pa = *reinterpret_cast<const float4*>(A + a_base + kt);
            pb = *reinterpret_cast<const float4*>(W + b_base + (size_t)kt * N);
        }

        // Compute on current stage.
#pragma unroll
        for (int k = 0; k < BK; ++k) {
            float a[8], b[8];
            float4 a0 = *reinterpret_cast<const float4*>(&As[cur][k][ty * 4]);
            float4 a1 = *reinterpret_cast<const float4*>(&As[cur][k][64 + ty * 4]);
            a[0]=a0.x; a[1]=a0.y; a[2]=a0.z; a[3]=a0.w;
            a[4]=a1.x; a[5]=a1.y; a[6]=a1.z; a[7]=a1.w;
            float4 b0 = *reinterpret_cast<const float4*>(&Bs[cur][k][tx * 4]);
            float4 b1 = *reinterpret_cast<const float4*>(&Bs[cur][k][64 + tx * 4]);
            b[0]=b0.x; b[1]=b0.y; b[2]=b0.z; b[3]=b0.w;
            b[4]=b1.x; b[5]=b1.y; b[6]=b1.z; b[7]=b1.w;
#pragma unroll
            for (int i = 0; i < 8; ++i)
#pragma unroll
                for (int j = 0; j < 8; ++j)
                    acc[i][j] = fmaf(a[i], b[j], acc[i][j]);
        }

        // Commit next tile to the other stage; single barrier per iteration.
        if (have_next) {
            const int nxt = cur ^ 1;
            As[nxt][a_f4 * 4 + 0][a_row] = pa.x;
            As[nxt][a_f4 * 4 + 1][a_row] = pa.y;
            As[nxt][a_f4 * 4 + 2][a_row] = pa.z;
            As[nxt][a_f4 * 4 + 3][a_row] = pa.w;
            *reinterpret_cast<float4*>(&Bs[nxt][b_row][b_c4 * 4]) = pb;
            __syncthreads();
        }
    }

    // Epilogue: bias (+ReLU)
    float4 bias0 = *reinterpret_cast<const float4*>(bias + bn0 + tx * 4);
    float4 bias1 = *reinterpret_cast<const float4*>(bias + bn0 + 64 + tx * 4);
#pragma unroll
    for (int rg = 0; rg < 2; ++rg) {
#pragma unroll
        for (int i = 0; i < 4; ++i) {
            int row = bm0 + rg * 64 + ty * 4 + i;
            if (row >= M) continue;
            int ai = rg * 4 + i;
#pragma unroll
            for (int cg = 0; cg < 2; ++cg) {
                float4 bv = cg ? bias1 : bias0;
                float4 v;
                v.x = acc[ai][cg * 4 + 0] + bv.x;
                v.y = acc[ai][cg * 4 + 1] + bv.y;
                v.z = acc[ai][cg * 4 + 2] + bv.z;
                v.w = acc[ai][cg * 4 + 3] + bv.w;
                if (RELU) {
                    v.x = fmaxf(v.x, 0.f); v.y = fmaxf(v.y, 0.f);
                    v.z = fmaxf(v.z, 0.f); v.w = fmaxf(v.w, 0.f);
                }
                *reinterpret_cast<float4*>(
                    C + (size_t)row * N + bn0 + cg * 64 + tx * 4) = v;
            }
        }
    }
}

// ---------------------------------------------------------------------------
// Dual-input GEMM, 128x64 tile (layer 2, N=64): 8x4 per thread, BK=16,
// double-buffered smem (1 barrier per k-tile) + register prefetch, mirroring
// the audited 128x128 pattern. M=50k -> 391 blocks, single wave.
// ---------------------------------------------------------------------------
template <bool RELU>
__global__ void __launch_bounds__(256)
gemm_dual_128x64(const float* __restrict__ A1, const float* __restrict__ W1,
                 const float* __restrict__ A2, const float* __restrict__ W2,
                 const float* __restrict__ bias, float* __restrict__ C,
                 int M, int N, int K)
{
    constexpr int BM = 128, BN = 64, BK = 16;
    __shared__ float As[2][BK][BM + 8];
    __shared__ float Bs[2][BK][BN];

    const int tid = threadIdx.x;
    const int tx  = tid % 16;          // col group (16 * TN=4 = 64)
    const int ty  = tid / 16;          // row group (16 * TM=8 = 128)
    const int bm0 = blockIdx.x * BM;
    const int bn0 = blockIdx.y * BN;

    // A tile: 128 rows x 16 cols = 512 float4; 2 per thread (rows r, r+64).
    const int a_f4c = tid % 4;         // which 16B chunk of the 64B k-row
    const int a_row = tid / 4;         // 0..63
    // B tile: 16 rows x 64 cols = 256 float4; 1 per thread.
    const int b_row = tid / 16;        // 0..15
    const int b_c4  = tid % 16;        // 0..15

    const bool a_in0 = (bm0 + a_row)      < M;
    const bool a_in1 = (bm0 + a_row + 64) < M;
    const size_t a_base0 = (size_t)(bm0 + a_row)      * K + a_f4c * 4;
    const size_t a_base1 = (size_t)(bm0 + a_row + 64) * K + a_f4c * 4;
    const size_t b_base  = (size_t)b_row * N + bn0 + b_c4 * 4;

    float acc[8][4];
#pragma unroll
    for (int i = 0; i < 8; ++i)
#pragma unroll
        for (int j = 0; j < 4; ++j) acc[i][j] = 0.f;

    const int NK = K / BK;             // k-tiles per phase
    const int total = 2 * NK;

    // Prologue: fetch tile 0 (phase 0) and commit to stage 0.
    {
        float4 pa0 = make_float4(0.f, 0.f, 0.f, 0.f);
        float4 pa1 = make_float4(0.f, 0.f, 0.f, 0.f);
        if (a_in0) pa0 = *reinterpret_cast<const float4*>(A1 + a_base0);
        if (a_in1) pa1 = *reinterpret_cast<const float4*>(A1 + a_base1);
        float4 pb = *reinterpret_cast<const float4*>(W1 + b_base);
        As[0][a_f4c * 4 + 0][a_row]      = pa0.x;
        As[0][a_f4c * 4 + 1][a_row]      = pa0.y;
        As[0][a_f4c * 4 + 2][a_row]      = pa0.z;
        As[0][a_f4c * 4 + 3][a_row]      = pa0.w;
        As[0][a_f4c * 4 + 0][a_row + 64] = pa1.x;
        As[0][a_f4c * 4 + 1][a_row + 64] = pa1.y;
        As[0][a_f4c * 4 + 2][a_row + 64] = pa1.z;
        As[0][a_f4c * 4 + 3][a_row + 64] = pa1.w;
        *reinterpret_cast<float4*>(&Bs[0][b_row][b_c4 * 4]) = pb;
    }
    __syncthreads();

#pragma unroll 1
    for (int t = 0; t < total; ++t) {
        const int cur = t & 1;

        float4 pa0, pa1, pb;
        const bool have_next = (t + 1 < total);
        if (have_next) {
            int nt = t + 1;
            const float* A = (nt < NK) ? A1 : A2;
            const float* W = (nt < NK) ? W1 : W2;
            int kt = (nt < NK ? nt : nt - NK) * BK;
            pa0 = make_float4(0.f, 0.f, 0.f, 0.f);
            pa1 = make_float4(0.f, 0.f, 0.f, 0.f);
            if (a_in0) pa0 = *reinterpret_cast<const float4*>(A + a_base0 + kt);
            if (a_in1) pa1 = *reinterpret_cast<const float4*>(A + a_base1 + kt);
            pb = *reinterpret_cast<const float4*>(W + b_base + (size_t)kt * N);
        }

        // Compute on current stage.
#pragma unroll
        for (int k = 0; k < BK; ++k) {
            float a[8], b[4];
            float4 a0 = *reinterpret_cast<const float4*>(&As[cur][k][ty * 8]);
            float4 a1 = *reinterpret_cast<const float4*>(&As[cur][k][ty * 8 + 4]);
            a[0]=a0.x; a[1]=a0.y; a[2]=a0.z; a[3]=a0.w;
            a[4]=a1.x; a[5]=a1.y; a[6]=a1.z; a[7]=a1.w;
            float4 bv = *reinterpret_cast<const float4*>(&Bs[cur][k][tx * 4]);
            b[0]=bv.x; b[1]=bv.y; b[2]=bv.z; b[3]=bv.w;
#pragma unroll
            for (int i = 0; i < 8; ++i)
#pragma unroll
                for (int j = 0; j < 4; ++j)
                    acc[i][j] = fmaf(a[i], b[j], acc[i][j]);
        }

        if (have_next) {
            const int nxt = cur ^ 1;
            As[nxt][a_f4c * 4 + 0][a_row]      = pa0.x;
            As[nxt][a_f4c * 4 + 1][a_row]      = pa0.y;
            As[nxt][a_f4c * 4 + 2][a_row]      = pa0.z;
            As[nxt][a_f4c * 4 + 3][a_row]      = pa0.w;
            As[nxt][a_f4c * 4 + 0][a_row + 64] = pa1.x;
            As[nxt][a_f4c * 4 + 1][a_row + 64] = pa1.y;
            As[nxt][a_f4c * 4 + 2][a_row + 64] = pa1.z;
            As[nxt][a_f4c * 4 + 3][a_row + 64] = pa1.w;
            *reinterpret_cast<float4*>(&Bs[nxt][b_row][b_c4 * 4]) = pb;
            __syncthreads();
        }
    }

    // Epilogue: bias (+ReLU)
    const int col = bn0 + tx * 4;
    float4 bv = *reinterpret_cast<const float4*>(bias + col);
#pragma unroll
    for (int i = 0; i < 8; ++i) {
        int row = bm0 + ty * 8 + i;
        if (row >= M) continue;
        float4 v;
        v.x = acc[i][0] + bv.x;
        v.y = acc[i][1] + bv.y;
        v.z = acc[i][2] + bv.z;
        v.w = acc[i][3] + bv.w;
        if (RELU) {
            v.x = fmaxf(v.x, 0.f); v.y = fmaxf(v.y, 0.f);
            v.z = fmaxf(v.z, 0.f); v.w = fmaxf(v.w, 0.f);
        }
        *reinterpret_cast<float4*>(C + (size_t)row * N + col) = v;
    }
}

// ---------------------------------------------------------------------------
// Launch
// ---------------------------------------------------------------------------
extern "C" void kernel_launch(void* const* d_in, const int* in_sizes, int n_in,
                              void* d_out, int out_size)
{
    // Map inputs positionally, skipping any size-1 scalars (num_dst0/num_dst1
    // may or may not be materialized as device tensors).
    const void* p[16];
    int c = 0;
    for (int i = 0; i < n_in && c < 16; ++i) {
        if (in_sizes[i] == 1) continue;
        p[c++] = d_in[i];
    }
    const float* x    = (const float*)p[0];   // [200000,128]
    const void*  src0 = p[1];                 // [1.6M] int32 or int64
    const void*  dst0 = p[2];                 // [1.6M] sorted
    const void*  src1 = p[3];                 // [800K]
    const void*  dst1 = p[4];                 // [800K] sorted
    const float* Ws1  = (const float*)p[5];   // [128,256]
    const float* Wn1  = (const float*)p[6];   // [128,256]
    const float* b1   = (const float*)p[7];   // [256]
    const float* Ws2  = (const float*)p[8];   // [256,64]
    const float* Wn2  = (const float*)p[9];   // [256,64]
    const float* b2   = (const float*)p[10];  // [64]

    float *neigh1, *h1, *neigh2;
    cudaGetSymbolAddress((void**)&neigh1, g_neigh1);
    cudaGetSymbolAddress((void**)&h1,     g_h1);
    cudaGetSymbolAddress((void**)&neigh2, g_neigh2);

    // Probe index dtype once per launch (deterministic, graph-capturable).
    detect_idx_dtype<<<1, 1>>>((const int*)src0);

    // Layer 1: mean-aggregate raw features, then fused dual GEMM + ReLU
    {
        int blocks = (CN1 * 32 + 255) / 256;
        agg_mean_kernel<1, 4><<<blocks, 256>>>(x, src0, dst0, CE0, CN1, neigh1);

        dim3 grid((CN1 + 127) / 128, CH_F / 128);
        gemm_dual_128x128<true><<<grid, 256>>>(
            x, Ws1, neigh1, Wn1, b1, h1, CN1, CH_F, CIN_F);
    }

    // Layer 2: aggregate over h1, then fused dual GEMM (no ReLU) -> d_out
    {
        int blocks = (CN2 * 32 + 255) / 256;
        agg_mean_kernel<2, 2><<<blocks, 256>>>(h1, src1, dst1, CE1, CN2, neigh2);

        dim3 grid((CN2 + 127) / 128, CN_CLS / 64);
        gemm_dual_128x64<false><<<grid, 256>>>(
            h1, Ws2, neigh2, Wn2, b2, (float*)d_out, CN2, CN_CLS, CH_F);
    }
}

// round 15
// speedup vs baseline: 1.0781x; 1.0781x over previous
#include <cuda_runtime.h>
#include <cstddef>
#include <cstdint>

// Problem constants (fixed by the reference's module-level constants)
#define CN0   200000
#define CN1   100000
#define CN2   50000
#define CE0   1600000
#define CE1   800000
#define CIN_F 128
#define CH_F  256
#define CN_CLS 64

// ---------------------------------------------------------------------------
// Scratch (no allocation allowed -> __device__ globals)
// ---------------------------------------------------------------------------
__device__ float g_neigh1[(size_t)CN1 * CIN_F];   //  51.2 MB
__device__ float g_h1[(size_t)CN1 * CH_F];        // 102.4 MB
__device__ float g_neigh2[(size_t)CN2 * CH_F];    //  51.2 MB
__device__ int   g_idx64;                         // 1 if index arrays are int64

// ---------------------------------------------------------------------------
// Index-dtype probe (unchanged, verified passing R13).
// ---------------------------------------------------------------------------
__global__ void detect_idx_dtype(const int* __restrict__ src0_as_i32)
{
    bool i64 = true;
#pragma unroll
    for (int i = 0; i < 8; ++i)
        if (src0_as_i32[2 * i + 1] != 0) { i64 = false; break; }
    g_idx64 = i64 ? 1 : 0;
}

__device__ __forceinline__ int load_idx(const void* p, int i, bool i64)
{
    return i64 ? (int)__ldg(&((const long long*)p)[i])
               : __ldg(&((const int*)p)[i]);
}

// ---------------------------------------------------------------------------
// Segment-mean aggregation (unchanged from passing R13 kernel).
// ---------------------------------------------------------------------------
template <int FPL, int UNROLL>
__global__ void __launch_bounds__(256)
agg_mean_kernel(const float* __restrict__ h,
                const void* __restrict__ src,
                const void* __restrict__ dst,
                int num_edges, int num_dst,
                float* __restrict__ out)
{
    const int F = FPL * 128;
    int warp = (blockIdx.x * blockDim.x + threadIdx.x) >> 5;
    int lane = threadIdx.x & 31;
    if (warp >= num_dst) return;
    const int d = warp;
    const bool i64 = (g_idx64 != 0);

    int lo = 0, hi = num_edges;
    while (lo < hi) {
        int mid = (lo + hi) >> 1;
        if (load_idx(dst, mid, i64) < d) lo = mid + 1; else hi = mid;
    }
    const int start = lo;
    hi = num_edges;
    while (lo < hi) {
        int mid = (lo + hi) >> 1;
        if (load_idx(dst, mid, i64) <= d) lo = mid + 1; else hi = mid;
    }
    const int end = lo;

    float4 acc[UNROLL][FPL];
#pragma unroll
    for (int u = 0; u < UNROLL; ++u)
#pragma unroll
        for (int i = 0; i < FPL; ++i)
            acc[u][i] = make_float4(0.f, 0.f, 0.f, 0.f);

    int e = start;
    for (; e + UNROLL - 1 < end; e += UNROLL) {
        const float4* rows[UNROLL];
#pragma unroll
        for (int u = 0; u < UNROLL; ++u) {
            int s = load_idx(src, e + u, i64);
            rows[u] = reinterpret_cast<const float4*>(h + (size_t)s * F);
        }
#pragma unroll
        for (int i = 0; i < FPL; ++i) {
#pragma unroll
            for (int u = 0; u < UNROLL; ++u) {
                float4 v = __ldg(&rows[u][lane + i * 32]);
                acc[u][i].x += v.x; acc[u][i].y += v.y;
                acc[u][i].z += v.z; acc[u][i].w += v.w;
            }
        }
    }
    for (; e < end; ++e) {
        int s = load_idx(src, e, i64);
        const float4* r = reinterpret_cast<const float4*>(h + (size_t)s * F);
#pragma unroll
        for (int i = 0; i < FPL; ++i) {
            float4 v = __ldg(&r[lane + i * 32]);
            acc[0][i].x += v.x; acc[0][i].y += v.y;
            acc[0][i].z += v.z; acc[0][i].w += v.w;
        }
    }

    int deg = end - start;
    float inv = 1.0f / (float)(deg > 1 ? deg : 1);
    float4* orow = reinterpret_cast<float4*>(out + (size_t)d * F);
#pragma unroll
    for (int i = 0; i < FPL; ++i) {
        float4 v = acc[0][i];
#pragma unroll
        for (int u = 1; u < UNROLL; ++u) {
            v.x += acc[u][i].x; v.y += acc[u][i].y;
            v.z += acc[u][i].z; v.w += acc[u][i].w;
        }
        v.x *= inv; v.y *= inv; v.z *= inv; v.w *= inv;
        orow[lane + i * 32] = v;
    }
}

// ---------------------------------------------------------------------------
// TF32 helpers: split fp32 into hi (tf32) + lo (tf32 of residual).
// 3xTF32: A*B ~= Ahi*Bhi + Ahi*Blo + Alo*Bhi  (error ~1e-7 relative).
// ---------------------------------------------------------------------------
__device__ __forceinline__ void split_tf32(float v, uint32_t& hi, uint32_t& lo)
{
    uint32_t h;
    asm("cvt.rna.tf32.f32 %0, %1;" : "=r"(h) : "f"(v));
    float r = v - __uint_as_float(h);
    uint32_t l;
    asm("cvt.rna.tf32.f32 %0, %1;" : "=r"(l) : "f"(r));
    hi = h; lo = l;
}

__device__ __forceinline__ void mma_m16n8k8_tf32(float* c, const uint32_t* a,
                                                 const uint32_t* b)
{
    asm volatile(
        "mma.sync.aligned.m16n8k8.row.col.f32.tf32.tf32.f32 "
        "{%0,%1,%2,%3}, {%4,%5,%6,%7}, {%8,%9}, {%0,%1,%2,%3};\n"
        : "+f"(c[0]), "+f"(c[1]), "+f"(c[2]), "+f"(c[3])
        : "r"(a[0]), "r"(a[1]), "r"(a[2]), "r"(a[3]), "r"(b[0]), "r"(b[1]));
}

// ---------------------------------------------------------------------------
// Dual-input GEMM via 3xTF32 tensor cores. 128x128 block, 8 warps (4x2),
// warp tile 32x64 = 2x8 m16n8k8 tiles. Double-buffered smem holds hi/lo
// tf32 tiles (split at fill time). Register prefetch of next k-tile.
//   C = A1 @ W1 + A2 @ W2 + bias  (+ReLU)
// Requires K%8==0, N%128==0.
// ---------------------------------------------------------------------------
template <bool RELU>
__global__ void __launch_bounds__(256)
gemm_dual_tf32_128x128(const float* __restrict__ A1, const float* __restrict__ W1,
                       const float* __restrict__ A2, const float* __restrict__ W2,
                       const float* __restrict__ bias, float* __restrict__ C,
                       int M, int N, int K)
{
    constexpr int BM = 128, BN = 128, BK = 8;
    __shared__ uint32_t AsH[2][BK][BM + 4];
    __shared__ uint32_t AsL[2][BK][BM + 4];
    __shared__ uint32_t BsH[2][BK][BN + 4];
    __shared__ uint32_t BsL[2][BK][BN + 4];

    const int tid    = threadIdx.x;
    const int lane   = tid & 31;
    const int wid    = tid >> 5;
    const int warp_m = wid & 3;        // 0..3 -> 32-row slab
    const int warp_n = wid >> 2;       // 0..1 -> 64-col slab
    const int bm0    = blockIdx.x * BM;
    const int bn0    = blockIdx.y * BN;

    // Global->smem load mapping (1 float4 per thread per tile each for A, B)
    const int a_row = tid >> 1;        // 0..127
    const int a_f4  = tid & 1;         // which 16B of the 32B k-row
    const int b_row = tid >> 5;        // 0..7
    const int b_c4  = tid & 31;

    const bool a_in = (bm0 + a_row) < M;
    const size_t a_base = (size_t)(bm0 + a_row) * K + a_f4 * 4;
    const size_t b_base = (size_t)b_row * N + bn0 + b_c4 * 4;

    float acc[2][8][4];
#pragma unroll
    for (int i = 0; i < 2; ++i)
#pragma unroll
        for (int j = 0; j < 8; ++j)
#pragma unroll
            for (int q = 0; q < 4; ++q) acc[i][j][q] = 0.f;

    const int NK = K / BK;
    const int total = 2 * NK;

    // Prologue: fetch + split tile 0 into stage 0.
    {
        float4 pa = make_float4(0.f, 0.f, 0.f, 0.f);
        if (a_in) pa = *reinterpret_cast<const float4*>(A1 + a_base);
        float4 pb = *reinterpret_cast<const float4*>(W1 + b_base);
        const float av[4] = {pa.x, pa.y, pa.z, pa.w};
        const float bv[4] = {pb.x, pb.y, pb.z, pb.w};
#pragma unroll
        for (int e = 0; e < 4; ++e) {
            uint32_t h, l;
            split_tf32(av[e], h, l);
            AsH[0][a_f4 * 4 + e][a_row] = h;
            AsL[0][a_f4 * 4 + e][a_row] = l;
            split_tf32(bv[e], h, l);
            BsH[0][b_row][b_c4 * 4 + e] = h;
            BsL[0][b_row][b_c4 * 4 + e] = l;
        }
    }
    __syncthreads();

#pragma unroll 1
    for (int t = 0; t < total; ++t) {
        const int cur = t & 1;

        // Prefetch next tile (global -> registers).
        float4 pa, pb;
        const bool have_next = (t + 1 < total);
        if (have_next) {
            int nt = t + 1;
            const float* A = (nt < NK) ? A1 : A2;
            const float* W = (nt < NK) ? W1 : W2;
            int kt = (nt < NK ? nt : nt - NK) * BK;
            pa = make_float4(0.f, 0.f, 0.f, 0.f);
            if (a_in) pa = *reinterpret_cast<const float4*>(A + a_base + kt);
            pb = *reinterpret_cast<const float4*>(W + b_base + (size_t)kt * N);
        }

        // ---- Compute on current stage ----
        // A fragments (held across all 8 n-tiles): m16n8k8 row-major A map:
        //  a0:(g, c) a1:(g+8, c) a2:(g, c+4) a3:(g+8, c+4), g=lane/4, c=lane%4
        uint32_t ah[2][4], al[2][4];
        {
            const int c0 = lane & 3;
            const int r0 = (warp_m << 5) + (lane >> 2);
#pragma unroll
            for (int i = 0; i < 2; ++i) {
                const int rb = r0 + i * 16;
                ah[i][0] = AsH[cur][c0    ][rb    ];
                ah[i][1] = AsH[cur][c0    ][rb + 8];
                ah[i][2] = AsH[cur][c0 + 4][rb    ];
                ah[i][3] = AsH[cur][c0 + 4][rb + 8];
                al[i][0] = AsL[cur][c0    ][rb    ];
                al[i][1] = AsL[cur][c0    ][rb + 8];
                al[i][2] = AsL[cur][c0 + 4][rb    ];
                al[i][3] = AsL[cur][c0 + 4][rb + 8];
            }
        }
#pragma unroll
        for (int j = 0; j < 8; ++j) {
            // B fragment: col-major 8x8 map: b0:(k=lane%4, n=lane/4), b1:(k+4, n)
            const int bn = (warp_n << 6) + j * 8 + (lane >> 2);
            const int kr = lane & 3;
            uint32_t bh[2], bl[2];
            bh[0] = BsH[cur][kr    ][bn];
            bh[1] = BsH[cur][kr + 4][bn];
            bl[0] = BsL[cur][kr    ][bn];
            bl[1] = BsL[cur][kr + 4][bn];
#pragma unroll
            for (int i = 0; i < 2; ++i) {
                mma_m16n8k8_tf32(acc[i][j], ah[i], bh);
                mma_m16n8k8_tf32(acc[i][j], al[i], bh);
                mma_m16n8k8_tf32(acc[i][j], ah[i], bl);
            }
        }

        // Commit next tile (split) to the other stage; one barrier per tile.
        if (have_next) {
            const int nxt = cur ^ 1;
            const float av[4] = {pa.x, pa.y, pa.z, pa.w};
            const float bv[4] = {pb.x, pb.y, pb.z, pb.w};
#pragma unroll
            for (int e = 0; e < 4; ++e) {
                uint32_t h, l;
                split_tf32(av[e], h, l);
                AsH[nxt][a_f4 * 4 + e][a_row] = h;
                AsL[nxt][a_f4 * 4 + e][a_row] = l;
                split_tf32(bv[e], h, l);
                BsH[nxt][b_row][b_c4 * 4 + e] = h;
                BsL[nxt][b_row][b_c4 * 4 + e] = l;
            }
            __syncthreads();
        }
    }

    // Epilogue: C frag map c0:(g,2c) c1:(g,2c+1) c2:(g+8,2c) c3:(g+8,2c+1)
#pragma unroll
    for (int i = 0; i < 2; ++i) {
#pragma unroll
        for (int j = 0; j < 8; ++j) {
            const int r  = bm0 + (warp_m << 5) + i * 16 + (lane >> 2);
            const int cb = bn0 + (warp_n << 6) + j * 8 + 2 * (lane & 3);
            const float bias0 = __ldg(&bias[cb]);
            const float bias1 = __ldg(&bias[cb + 1]);
            if (r < M) {
                float2 v;
                v.x = acc[i][j][0] + bias0;
                v.y = acc[i][j][1] + bias1;
                if (RELU) { v.x = fmaxf(v.x, 0.f); v.y = fmaxf(v.y, 0.f); }
                *reinterpret_cast<float2*>(C + (size_t)r * N + cb) = v;
            }
            if (r + 8 < M) {
                float2 v;
                v.x = acc[i][j][2] + bias0;
                v.y = acc[i][j][3] + bias1;
                if (RELU) { v.x = fmaxf(v.x, 0.f); v.y = fmaxf(v.y, 0.f); }
                *reinterpret_cast<float2*>(C + (size_t)(r + 8) * N + cb) = v;
            }
        }
    }
}

// ---------------------------------------------------------------------------
// Dual-input GEMM, 128x64 FFMA tile (layer 2, N=64) — unchanged from R13.
// ---------------------------------------------------------------------------
template <bool RELU>
__global__ void __launch_bounds__(256)
gemm_dual_128x64(const float* __restrict__ A1, const float* __restrict__ W1,
                 const float* __restrict__ A2, const float* __restrict__ W2,
                 const float* __restrict__ bias, float* __restrict__ C,
                 int M, int N, int K)
{
    constexpr int BM = 128, BN = 64, BK = 16;
    __shared__ float As[2][BK][BM + 8];
    __shared__ float Bs[2][BK][BN];

    const int tid = threadIdx.x;
    const int tx  = tid % 16;
    const int ty  = tid / 16;
    const int bm0 = blockIdx.x * BM;
    const int bn0 = blockIdx.y * BN;

    const int a_f4c = tid % 4;
    const int a_row = tid / 4;
    const int b_row = tid / 16;
    const int b_c4  = tid % 16;

    const bool a_in0 = (bm0 + a_row)      < M;
    const bool a_in1 = (bm0 + a_row + 64) < M;
    const size_t a_base0 = (size_t)(bm0 + a_row)      * K + a_f4c * 4;
    const size_t a_base1 = (size_t)(bm0 + a_row + 64) * K + a_f4c * 4;
    const size_t b_base  = (size_t)b_row * N + bn0 + b_c4 * 4;

    float acc[8][4];
#pragma unroll
    for (int i = 0; i < 8; ++i)
#pragma unroll
        for (int j = 0; j < 4; ++j) acc[i][j] = 0.f;

    const int NK = K / BK;
    const int total = 2 * NK;

    {
        float4 pa0 = make_float4(0.f, 0.f, 0.f, 0.f);
        float4 pa1 = make_float4(0.f, 0.f, 0.f, 0.f);
        if (a_in0) pa0 = *reinterpret_cast<const float4*>(A1 + a_base0);
        if (a_in1) pa1 = *reinterpret_cast<const float4*>(A1 + a_base1);
        float4 pb = *reinterpret_cast<const float4*>(W1 + b_base);
        As[0][a_f4c * 4 + 0][a_row]      = pa0.x;
        As[0][a_f4c * 4 + 1][a_row]      = pa0.y;
        As[0][a_f4c * 4 + 2][a_row]      = pa0.z;
        As[0][a_f4c * 4 + 3][a_row]      = pa0.w;
        As[0][a_f4c * 4 + 0][a_row + 64] = pa1.x;
        As[0][a_f4c * 4 + 1][a_row + 64] = pa1.y;
        As[0][a_f4c * 4 + 2][a_row + 64] = pa1.z;
        As[0][a_f4c * 4 + 3][a_row + 64] = pa1.w;
        *reinterpret_cast<float4*>(&Bs[0][b_row][b_c4 * 4]) = pb;
    }
    __syncthreads();

#pragma unroll 1
    for (int t = 0; t < total; ++t) {
        const int cur = t & 1;

        float4 pa0, pa1, pb;
        const bool have_next = (t + 1 < total);
        if (have_next) {
            int nt = t + 1;
            const float* A = (nt < NK) ? A1 : A2;
            const float* W = (nt < NK) ? W1 : W2;
            int kt = (nt < NK ? nt : nt - NK) * BK;
            pa0 = make_float4(0.f, 0.f, 0.f, 0.f);
            pa1 = make_float4(0.f, 0.f, 0.f, 0.f);
            if (a_in0) pa0 = *reinterpret_cast<const float4*>(A + a_base0 + kt);
            if (a_in1) pa1 = *reinterpret_cast<const float4*>(A + a_base1 + kt);
            pb = *reinterpret_cast<const float4*>(W + b_base + (size_t)kt * N);
        }

#pragma unroll
        for (int k = 0; k < BK; ++k) {
            float a[8], b[4];
            float4 a0 = *reinterpret_cast<const float4*>(&As[cur][k][ty * 8]);
            float4 a1 = *reinterpret_cast<const float4*>(&As[cur][k][ty * 8 + 4]);
            a[0]=a0.x; a[1]=a0.y; a[2]=a0.z; a[3]=a0.w;
            a[4]=a1.x; a[5]=a1.y; a[6]=a1.z; a[7]=a1.w;
            float4 bv = *reinterpret_cast<const float4*>(&Bs[cur][k][tx * 4]);
            b[0]=bv.x; b[1]=bv.y; b[2]=bv.z; b[3]=bv.w;
#pragma unroll
            for (int i = 0; i < 8; ++i)
#pragma unroll
                for (int j = 0; j < 4; ++j)
                    acc[i][j] = fmaf(a[i], b[j], acc[i][j]);
        }

        if (have_next) {
            const int nxt = cur ^ 1;
            As[nxt][a_f4c * 4 + 0][a_row]      = pa0.x;
            As[nxt][a_f4c * 4 + 1][a_row]      = pa0.y;
            As[nxt][a_f4c * 4 + 2][a_row]      = pa0.z;
            As[nxt][a_f4c * 4 + 3][a_row]      = pa0.w;
            As[nxt][a_f4c * 4 + 0][a_row + 64] = pa1.x;
            As[nxt][a_f4c * 4 + 1][a_row + 64] = pa1.y;
            As[nxt][a_f4c * 4 + 2][a_row + 64] = pa1.z;
            As[nxt][a_f4c * 4 + 3][a_row + 64] = pa1.w;
            *reinterpret_cast<float4*>(&Bs[nxt][b_row][b_c4 * 4]) = pb;
            __syncthreads();
        }
    }

    const int col = bn0 + tx * 4;
    float4 bv = *reinterpret_cast<const float4*>(bias + col);
#pragma unroll
    for (int i = 0; i < 8; ++i) {
        int row = bm0 + ty * 8 + i;
        if (row >= M) continue;
        float4 v;
        v.x = acc[i][0] + bv.x;
        v.y = acc[i][1] + bv.y;
        v.z = acc[i][2] + bv.z;
        v.w = acc[i][3] + bv.w;
        if (RELU) {
            v.x = fmaxf(v.x, 0.f); v.y = fmaxf(v.y, 0.f);
            v.z = fmaxf(v.z, 0.f); v.w = fmaxf(v.w, 0.f);
        }
        *reinterpret_cast<float4*>(C + (size_t)row * N + col) = v;
    }
}

// ---------------------------------------------------------------------------
// Launch
// ---------------------------------------------------------------------------
extern "C" void kernel_launch(void* const* d_in, const int* in_sizes, int n_in,
                              void* d_out, int out_size)
{
    const void* p[16];
    int c = 0;
    for (int i = 0; i < n_in && c < 16; ++i) {
        if (in_sizes[i] == 1) continue;
        p[c++] = d_in[i];
    }
    const float* x    = (const float*)p[0];   // [200000,128]
    const void*  src0 = p[1];                 // [1.6M] int32 or int64
    const void*  dst0 = p[2];                 // [1.6M] sorted
    const void*  src1 = p[3];                 // [800K]
    const void*  dst1 = p[4];                 // [800K] sorted
    const float* Ws1  = (const float*)p[5];   // [128,256]
    const float* Wn1  = (const float*)p[6];   // [128,256]
    const float* b1   = (const float*)p[7];   // [256]
    const float* Ws2  = (const float*)p[8];   // [256,64]
    const float* Wn2  = (const float*)p[9];   // [256,64]
    const float* b2   = (const float*)p[10];  // [64]

    float *neigh1, *h1, *neigh2;
    cudaGetSymbolAddress((void**)&neigh1, g_neigh1);
    cudaGetSymbolAddress((void**)&h1,     g_h1);
    cudaGetSymbolAddress((void**)&neigh2, g_neigh2);

    detect_idx_dtype<<<1, 1>>>((const int*)src0);

    // Layer 1: mean-aggregate raw features, then 3xTF32 dual GEMM + ReLU
    {
        int blocks = (CN1 * 32 + 255) / 256;
        agg_mean_kernel<1, 4><<<blocks, 256>>>(x, src0, dst0, CE0, CN1, neigh1);

        dim3 grid((CN1 + 127) / 128, CH_F / 128);
        gemm_dual_tf32_128x128<true><<<grid, 256>>>(
            x, Ws1, neigh1, Wn1, b1, h1, CN1, CH_F, CIN_F);
    }

    // Layer 2: aggregate over h1, then FFMA dual GEMM (no ReLU) -> d_out
    {
        int blocks = (CN2 * 32 + 255) / 256;
        agg_mean_kernel<2, 2><<<blocks, 256>>>(h1, src1, dst1, CE1, CN2, neigh2);

        dim3 grid((CN2 + 127) / 128, CN_CLS / 64);
        gemm_dual_128x64<false><<<grid, 256>>>(
            h1, Ws2, neigh2, Wn2, b2, (float*)d_out, CN2, CN_CLS, CH_F);
    }
}